// round 6
// baseline (speedup 1.0000x reference)
#include <cuda_runtime.h>
#include <cuda_bf16.h>

#define SEQL 2048
#define BATCH 2
#define HIDD 1024
#define NH 16
#define DHD 64
#define NR 101

__device__ float g_Qp[BATCH*NH*SEQL*DHD];
__device__ float g_Kp[BATCH*NH*SEQL*DHD];
__device__ float g_Vp[BATCH*NH*SEQL*DHD];
__device__ float g_Ctx[BATCH*SEQL*HIDD];
__device__ float g_Xq[SEQL*BATCH*HIDD];
__device__ float g_Xk[SEQL*BATCH*HIDD];
__device__ float g_Xv[SEQL*BATCH*HIDD];
__device__ float g_Wqp[HIDD*HIDD];
__device__ float g_Wkp[HIDD*HIDD];
__device__ float g_Wvp[HIDD*HIDD];
__device__ float g_Wop[HIDD*HIDD];

__device__ __forceinline__ unsigned f2tf(float f) {
    unsigned u;
    asm("cvt.rna.tf32.f32 %0, %1;" : "=r"(u) : "f"(f));
    return u;
}
__device__ __forceinline__ float f2tff(float f) { return __uint_as_float(f2tf(f)); }

__device__ __forceinline__ void mma_tf32(float* c, const unsigned* a, const unsigned* b) {
    asm volatile(
        "mma.sync.aligned.m16n8k8.row.col.f32.tf32.tf32.f32 "
        "{%0,%1,%2,%3}, {%4,%5,%6,%7}, {%8,%9}, {%0,%1,%2,%3};"
        : "+f"(c[0]), "+f"(c[1]), "+f"(c[2]), "+f"(c[3])
        : "r"(a[0]), "r"(a[1]), "r"(a[2]), "r"(a[3]), "r"(b[0]), "r"(b[1]));
}

// ---------------------------------------------------------------------------
// Pre-pass: tf32-round + permute k within 8-groups as (0,4,1,5,2,6,3,7).
// ---------------------------------------------------------------------------
__global__ __launch_bounds__(256) void preperm(
    const float* __restrict__ q, const float* __restrict__ k, const float* __restrict__ v,
    const float* __restrict__ wq, const float* __restrict__ wk,
    const float* __restrict__ wv, const float* __restrict__ wo,
    float* oq, float* ok, float* ov, float* owq, float* owk, float* owv, float* owo)
{
    const float* src; float* dst; int n8;
    switch (blockIdx.y) {
        case 0: src = q;  dst = oq;  n8 = SEQL*BATCH*HIDD/8; break;
        case 1: src = k;  dst = ok;  n8 = SEQL*BATCH*HIDD/8; break;
        case 2: src = v;  dst = ov;  n8 = SEQL*BATCH*HIDD/8; break;
        case 3: src = wq; dst = owq; n8 = HIDD*HIDD/8; break;
        case 4: src = wk; dst = owk; n8 = HIDD*HIDD/8; break;
        case 5: src = wv; dst = owv; n8 = HIDD*HIDD/8; break;
        default: src = wo; dst = owo; n8 = HIDD*HIDD/8; break;
    }
    int g = blockIdx.x * 256 + threadIdx.x;
    if (g >= n8) return;
    const float4* p = (const float4*)(src + (size_t)g * 8);
    float4 x = p[0], y = p[1];
    float4 o0 = make_float4(f2tff(x.x), f2tff(y.x), f2tff(x.y), f2tff(y.y));
    float4 o1 = make_float4(f2tff(x.z), f2tff(y.z), f2tff(x.w), f2tff(y.w));
    float4* d = (float4*)(dst + (size_t)g * 8);
    d[0] = o0; d[1] = o1;
}

// ---------------------------------------------------------------------------
// tf32 GEMM: 128 thr, 4 warps (2x2), warp tile 64x64, block 128x128, BK=16.
// ---------------------------------------------------------------------------
#define GEMM_BODY(MODE, PERMQK)                                                \
    __shared__ float As[2][128*24];                                            \
    __shared__ float Bs[2][128*24];                                            \
    const int tid  = threadIdx.x;                                              \
    const int lane = tid & 31, warp = tid >> 5;                                \
    const int grp = lane >> 2, l4 = lane & 3;                                  \
    const int wm = (warp >> 1) * 64;                                           \
    const int wn = (warp & 1) * 64;                                            \
    const int m0 = blockIdx.x * 128, n0 = blockIdx.y * 128;                    \
    float acc[4][8][4];                                                        \
    _Pragma("unroll")                                                          \
    for (int i = 0; i < 4; i++)                                                \
        _Pragma("unroll")                                                      \
        for (int j = 0; j < 8; j++)                                            \
            _Pragma("unroll")                                                  \
            for (int r = 0; r < 4; r++) acc[i][j][r] = 0.f;                    \
    const int r0 = tid >> 2, cc = (tid & 3) * 4;                               \
    const float *ap[4], *bp[4];                                                \
    _Pragma("unroll")                                                          \
    for (int s = 0; s < 4; s++) {                                              \
        int m = m0 + r0 + s*32;                                                \
        if (MODE == 0) {                                                       \
            int b = m >> 11, l = m & 2047;                                     \
            ap[s] = A + ((size_t)(l*BATCH+b))*HIDD + cc;                       \
        } else {                                                               \
            ap[s] = A + (size_t)m*HIDD + cc;                                   \
        }                                                                      \
        bp[s] = W + (size_t)(n0 + r0 + s*32)*HIDD + cc;                        \
    }                                                                          \
    float4 va[4], vb[4];                                                       \
    _Pragma("unroll")                                                          \
    for (int s = 0; s < 4; s++) { va[s] = *(const float4*)ap[s];               \
                                  vb[s] = *(const float4*)bp[s]; }             \
    auto sts = [&](int buf) {                                                  \
        _Pragma("unroll")                                                      \
        for (int s = 0; s < 4; s++) {                                          \
            *(float4*)&As[buf][(r0+s*32)*24+cc] = va[s];                       \
            *(float4*)&Bs[buf][(r0+s*32)*24+cc] = vb[s];                       \
        }                                                                      \
    };                                                                         \
    sts(0);                                                                    \
    __syncthreads();                                                           \
    int cur = 0;                                                               \
    for (int kt = 0; kt < 64; kt++) {                                          \
        if (kt + 1 < 64) {                                                     \
            int ko = (kt + 1) * 16;                                            \
            _Pragma("unroll")                                                  \
            for (int s = 0; s < 4; s++) {                                      \
                va[s] = *(const float4*)(ap[s] + ko);                          \
                vb[s] = *(const float4*)(bp[s] + ko);                          \
            }                                                                  \
        }                                                                      \
        const float* as = As[cur]; const float* bs = Bs[cur];                  \
        _Pragma("unroll")                                                      \
        for (int c = 0; c < 2; c++) {                                          \
            unsigned af[4][4], bf[8][2];                                       \
            _Pragma("unroll")                                                  \
            for (int i = 0; i < 4; i++) {                                      \
                int rr = wm + i*16 + grp;                                      \
                uint2 t0 = *(const uint2*)&as[rr*24 + c*8 + 2*l4];             \
                uint2 t1 = *(const uint2*)&as[(rr+8)*24 + c*8 + 2*l4];         \
                af[i][0] = t0.x; af[i][1] = t1.x;                              \
                af[i][2] = t0.y; af[i][3] = t1.y;                              \
            }                                                                  \
            _Pragma("unroll")                                                  \
            for (int j = 0; j < 8; j++) {                                      \
                int nn = wn + j*8 + grp;                                       \
                uint2 tb = *(const uint2*)&bs[nn*24 + c*8 + 2*l4];             \
                bf[j][0] = tb.x; bf[j][1] = tb.y;                              \
            }                                                                  \
            _Pragma("unroll")                                                  \
            for (int i = 0; i < 4; i++)                                        \
                _Pragma("unroll")                                              \
                for (int j = 0; j < 8; j++)                                    \
                    mma_tf32(acc[i][j], af[i], bf[j]);                         \
        }                                                                      \
        if (kt + 1 < 64) sts(cur ^ 1);                                         \
        __syncthreads();                                                       \
        cur ^= 1;                                                              \
    }                                                                          \
    const int pA = (l4 & 1) * 4 + (l4 >> 1);                                   \
    _Pragma("unroll")                                                          \
    for (int i = 0; i < 4; i++) {                                              \
        _Pragma("unroll")                                                      \
        for (int j = 0; j < 8; j++) {                                          \
            int cB = n0 + wn + j*8;                                            \
            int c0 = cB + l4*2;                                                \
            float bsv0 = bias[c0], bsv1 = bias[c0+1];                          \
            int d0, d1;                                                        \
            if (MODE == 0 && PERMQK) { d0 = cB + pA; d1 = cB + pA + 2; }       \
            else                     { d0 = c0;      d1 = c0 + 1;     }        \
            _Pragma("unroll")                                                  \
            for (int pr = 0; pr < 2; pr++) {                                   \
                int row = m0 + wm + i*16 + grp + pr*8;                         \
                int b = row >> 11, l = row & 2047;                             \
                float v0 = acc[i][j][pr*2+0] + bsv0;                           \
                float v1 = acc[i][j][pr*2+1] + bsv1;                           \
                if (MODE == 0) {                                               \
                    int h = c0 >> 6;                                           \
                    float* p = out + (((size_t)(b*NH+h))*SEQL + l)*DHD;        \
                    p[d0 & 63] = f2tff(v0);                                    \
                    p[d1 & 63] = f2tff(v1);                                    \
                } else {                                                       \
                    float* p = out + ((size_t)(l*BATCH+b))*HIDD;               \
                    p[d0] = v0; p[d1] = v1;                                    \
                }                                                              \
            }                                                                  \
        }                                                                      \
    }

__global__ __launch_bounds__(128, 2) void gemm_qkv(
    const float* __restrict__ bq, const float* __restrict__ bk, const float* __restrict__ bv,
    float* oq, float* ok, float* ov)
{
    const float *A, *W, *bias; float* out; bool permqk;
    if (blockIdx.z == 0)      { A = g_Xq; W = g_Wqp; bias = bq; out = oq; permqk = true; }
    else if (blockIdx.z == 1) { A = g_Xk; W = g_Wkp; bias = bk; out = ok; permqk = true; }
    else                      { A = g_Xv; W = g_Wvp; bias = bv; out = ov; permqk = false; }
    GEMM_BODY(0, permqk)
}

__global__ __launch_bounds__(128, 2) void gemm_out(
    const float* __restrict__ A, const float* __restrict__ W,
    const float* __restrict__ bias, float* __restrict__ out)
{
    GEMM_BODY(1, false)
}

// ---------------------------------------------------------------------------
// tf32 flash relative-attention: 256 thr (8 warps), q-tile 256 (warp: 32 rows,
// 2 row-groups), k-tiles 64. One-pass (bounded scores). P in Q-alias smem
// (warp-private rows). K/V register double-buffer. Band bf16, clips in regs.
// ---------------------------------------------------------------------------
#define STK 72
#define OFFP 0                 // Q then P: [256][72]
#define OFFK 18432             // K [64][72]; prelude rel_k [104][72]; epi rel_v [101][64]
#define OFFV 23040             // V [64][72]
#define OFFQD 27648            // bf16 QD [256][104]  (13312 floats)
#define OFFBD 40960            // bf16 band [256][100] (12800 floats)
#define ATT_SMEM_BYTES (53760*4)
#define C8 0.18033688011112042f   // 0.125 * log2(e)

__global__ __launch_bounds__(256, 1) void attn_tf32(
    const float* __restrict__ rel_k, const float* __restrict__ rel_v)
{
    extern __shared__ float sm[];
    const unsigned* smu = (const unsigned*)sm;
    __nv_bfloat16* qdp = (__nv_bfloat16*)(sm + OFFQD);
    __nv_bfloat16* pbd = (__nv_bfloat16*)(sm + OFFBD);
    const int tid = threadIdx.x;
    const int lane = tid & 31, w = tid >> 5;
    const int grp = lane >> 2, l4 = lane & 3;
    const int bh = blockIdx.y;
    const int q0 = blockIdx.x * 256;
    const size_t base = (size_t)bh * SEQL * DHD;
    const int pA = (l4 & 1) * 4 + (l4 >> 1);
    int rlA[2][2];
    #pragma unroll
    for (int i = 0; i < 2; i++)
        #pragma unroll
        for (int hh = 0; hh < 2; hh++) rlA[i][hh] = w*32 + i*16 + hh*8 + grp;

    // Q tile fill (pre-rounded, D-permuted): 256 rows
    #pragma unroll
    for (int s = 0; s < 16; s++) {
        int i = tid + s*256; int r = i >> 4, c4 = (i & 15)*4;
        *(float4*)(sm + OFFP + r*STK + c4) =
            *(const float4*)(g_Qp + base + (size_t)(q0+r)*DHD + c4);
    }
    // rel_k rows 0..103 (zero-pad), D-permuted scatter
    #pragma unroll
    for (int s = 0; s < 7; s++) {
        int i = tid + s*256;
        if (i < 104*16) {
            int r = i >> 4, c4 = (i & 15)*4;
            float4 v = make_float4(0.f,0.f,0.f,0.f);
            if (r < NR) v = *(const float4*)(rel_k + r*DHD + c4);
            int g8 = c4 & ~7, o = (c4 & 4) ? 1 : 0;
            float* p = sm + OFFK + r*STK + g8 + o;
            p[0] = v.x; p[2] = v.y; p[4] = v.z; p[6] = v.w;
        }
    }
    __syncthreads();

    // persistent Q fragments
    unsigned qf[2][8][4];
    #pragma unroll
    for (int i = 0; i < 2; i++)
        #pragma unroll
        for (int c = 0; c < 8; c++) {
            uint2 t0 = *(const uint2*)&smu[OFFP + rlA[i][0]*STK + c*8 + 2*l4];
            uint2 t1 = *(const uint2*)&smu[OFFP + rlA[i][1]*STK + c*8 + 2*l4];
            qf[i][c][0] = t0.x; qf[i][c][1] = t1.x;
            qf[i][c][2] = t0.y; qf[i][c][3] = t1.y;
        }

    // qdot = Q . rel_k -> bf16 table
    #pragma unroll
    for (int j = 0; j < 13; j++) {
        float c4a[2][4];
        #pragma unroll
        for (int i = 0; i < 2; i++)
            #pragma unroll
            for (int r = 0; r < 4; r++) c4a[i][r] = 0.f;
        #pragma unroll
        for (int c = 0; c < 8; c++) {
            uint2 tb = *(const uint2*)&smu[OFFK + (j*8+grp)*STK + c*8 + 2*l4];
            unsigned bf[2] = {tb.x, tb.y};
            mma_tf32(c4a[0], qf[0][c], bf);
            mma_tf32(c4a[1], qf[1][c], bf);
        }
        int col = j*8 + l4*2;
        #pragma unroll
        for (int i = 0; i < 2; i++) {
            *(__nv_bfloat162*)(qdp + rlA[i][0]*104 + col) = __floats2bfloat162_rn(c4a[i][0], c4a[i][1]);
            *(__nv_bfloat162*)(qdp + rlA[i][1]*104 + col) = __floats2bfloat162_rn(c4a[i][2], c4a[i][3]);
        }
    }
    __syncthreads();

    // zero band buffer
    {
        unsigned* bw = (unsigned*)pbd;
        #pragma unroll
        for (int s = 0; s < 50; s++) bw[tid + s*256] = 0u;
    }
    // per-row clip-bias constants (pre-scaled)
    float qlC[2][2], qrC[2][2];
    #pragma unroll
    for (int i = 0; i < 2; i++)
        #pragma unroll
        for (int hh = 0; hh < 2; hh++) {
            qlC[i][hh] = __bfloat162float(qdp[rlA[i][hh]*104 + 0])   * C8;
            qrC[i][hh] = __bfloat162float(qdp[rlA[i][hh]*104 + 100]) * C8;
        }
    __syncthreads();

    float oacc[2][8][4];
    #pragma unroll
    for (int i = 0; i < 2; i++)
        #pragma unroll
        for (int j = 0; j < 8; j++)
            #pragma unroll
            for (int r = 0; r < 4; r++) oacc[i][j][r] = 0.f;
    float lft[2][2] = {{0.f,0.f},{0.f,0.f}}, rgt[2][2] = {{0.f,0.f},{0.f,0.f}};

    // preload first K/V tile into registers
    float4 kreg[4], vreg[4];
    #pragma unroll
    for (int s = 0; s < 4; s++) {
        int i = tid + s*256; int r = i >> 4, c4 = (i & 15)*4;
        kreg[s] = *(const float4*)(g_Kp + base + (size_t)r*DHD + c4);
        vreg[s] = *(const float4*)(g_Vp + base + (size_t)r*DHD + c4);
    }

    for (int kt = 0; kt < 32; kt++) {
        const int k0 = kt * 64;
        #pragma unroll
        for (int s = 0; s < 4; s++) {
            int i = tid + s*256; int r = i >> 4, c4 = (i & 15)*4;
            *(float4*)(sm + OFFK + r*STK + c4) = kreg[s];
            *(float4*)(sm + OFFV + r*STK + c4) = vreg[s];
        }
        __syncthreads();
        if (kt + 1 < 32) {
            #pragma unroll
            for (int s = 0; s < 4; s++) {
                int i = tid + s*256; int r = i >> 4, c4 = (i & 15)*4;
                size_t g = base + (size_t)(k0 + 64 + r)*DHD + c4;
                kreg[s] = *(const float4*)(g_Kp + g);
                vreg[s] = *(const float4*)(g_Vp + g);
            }
        }

        const int dq = k0 - q0;
        const bool nearT = (dq >= -64 && dq <= 256);
        const bool leftT = dq < 0;

        // S = Q K^T per j-group, then exp + classify + store P
        #pragma unroll
        for (int j = 0; j < 8; j++) {
            float sfr[2][4];
            #pragma unroll
            for (int i = 0; i < 2; i++)
                #pragma unroll
                for (int r = 0; r < 4; r++) sfr[i][r] = 0.f;
            #pragma unroll
            for (int c = 0; c < 8; c++) {
                uint2 tb = *(const uint2*)&smu[OFFK + (j*8+grp)*STK + c*8 + 2*l4];
                unsigned bf[2] = {tb.x, tb.y};
                mma_tf32(sfr[0], qf[0][c], bf);
                mma_tf32(sfr[1], qf[1][c], bf);
            }
            if (nearT) {
                #pragma unroll
                for (int i = 0; i < 2; i++)
                    #pragma unroll
                    for (int hh = 0; hh < 2; hh++) {
                        int rl = rlA[i][hh];
                        float pp[2];
                        #pragma unroll
                        for (int par = 0; par < 2; par++) {
                            int col = j*8 + l4*2 + par;
                            int dlt = k0 + col - (q0 + rl);
                            int ix = min(max(dlt, -50), 50) + 50;
                            float qd = __bfloat162float(qdp[rl*104 + ix]);
                            float pv = exp2f((sfr[i][hh*2+par] + qd) * C8);
                            if (dlt <= -50)     lft[i][hh] += pv;
                            else if (dlt >= 50) rgt[i][hh] += pv;
                            else pbd[rl*100 + dlt + 49] = __float2bfloat16(pv);
                            pp[par] = f2tff(pv);
                        }
                        sm[OFFP + rl*STK + j*8 + pA]     = pp[0];
                        sm[OFFP + rl*STK + j*8 + pA + 2] = pp[1];
                    }
            } else {
                #pragma unroll
                for (int i = 0; i < 2; i++)
                    #pragma unroll
                    for (int hh = 0; hh < 2; hh++) {
                        int rl = rlA[i][hh];
                        float qc = leftT ? qlC[i][hh] : qrC[i][hh];
                        float pv0 = exp2f(fmaf(sfr[i][hh*2+0], C8, qc));
                        float pv1 = exp2f(fmaf(sfr[i][hh*2+1], C8, qc));
                        if (leftT) lft[i][hh] += pv0 + pv1;
                        else       rgt[i][hh] += pv0 + pv1;
                        sm[OFFP + rl*STK + j*8 + pA]     = f2tff(pv0);
                        sm[OFFP + rl*STK + j*8 + pA + 2] = f2tff(pv1);
                    }
            }
        }
        __syncwarp();

        // O += P V  (V B-frags reused across both row-groups)
        #pragma unroll
        for (int c = 0; c < 8; c++) {
            unsigned af[2][4];
            #pragma unroll
            for (int i = 0; i < 2; i++) {
                uint2 t0 = *(const uint2*)&smu[OFFP + rlA[i][0]*STK + c*8 + 2*l4];
                uint2 t1 = *(const uint2*)&smu[OFFP + rlA[i][1]*STK + c*8 + 2*l4];
                af[i][0] = t0.x; af[i][1] = t1.x; af[i][2] = t0.y; af[i][3] = t1.y;
            }
            #pragma unroll
            for (int j = 0; j < 8; j++) {
                unsigned bf[2];
                bf[0] = smu[OFFV + (c*8+l4)*STK + j*8 + grp];
                bf[1] = smu[OFFV + (c*8+l4+4)*STK + j*8 + grp];
                mma_tf32(oacc[0][j], af[0], bf);
                mma_tf32(oacc[1][j], af[1], bf);
            }
        }
        __syncthreads();
    }

    // quad-reduce clip masses
    #pragma unroll
    for (int i = 0; i < 2; i++)
        #pragma unroll
        for (int hh = 0; hh < 2; hh++) {
            lft[i][hh] += __shfl_xor_sync(0xffffffffu, lft[i][hh], 1);
            lft[i][hh] += __shfl_xor_sync(0xffffffffu, lft[i][hh], 2);
            rgt[i][hh] += __shfl_xor_sync(0xffffffffu, rgt[i][hh], 1);
            rgt[i][hh] += __shfl_xor_sync(0xffffffffu, rgt[i][hh], 2);
        }

    // rel_v plain [101][64] into dead K/V region
    #pragma unroll
    for (int s = 0; s < 7; s++) {
        int i = tid + s*256;
        if (i < NR*16) {
            int r = i >> 4, c4 = (i & 15)*4;
            *(float4*)(sm + OFFK + r*64 + c4) = *(const float4*)(rel_v + r*DHD + c4);
        }
    }
    __syncthreads();

    // w2 = band . rel_v[1..99] + lft*rel_v[0] + rgt*rel_v[100]
    float w2a[2][8][4];
    #pragma unroll
    for (int i = 0; i < 2; i++)
        #pragma unroll
        for (int j = 0; j < 8; j++)
            #pragma unroll
            for (int r = 0; r < 4; r++) w2a[i][j][r] = 0.f;
    float bsum[2][2] = {{0.f,0.f},{0.f,0.f}};
    for (int bnd = 0; bnd < 99; bnd++) {
        float pv[2][2];
        #pragma unroll
        for (int i = 0; i < 2; i++)
            #pragma unroll
            for (int hh = 0; hh < 2; hh++) {
                pv[i][hh] = __bfloat162float(pbd[rlA[i][hh]*100 + bnd]);
                bsum[i][hh] += pv[i][hh];
            }
        const float* rv = sm + OFFK + (bnd+1)*64 + l4*2;
        #pragma unroll
        for (int j = 0; j < 8; j++) {
            float r0v = rv[j*8], r1v = rv[j*8+1];
            #pragma unroll
            for (int i = 0; i < 2; i++) {
                w2a[i][j][0] += pv[i][0]*r0v; w2a[i][j][1] += pv[i][0]*r1v;
                w2a[i][j][2] += pv[i][1]*r0v; w2a[i][j][3] += pv[i][1]*r1v;
            }
        }
    }
    {
        const float* rvL = sm + OFFK + 0*64   + l4*2;
        const float* rvR = sm + OFFK + 100*64 + l4*2;
        #pragma unroll
        for (int j = 0; j < 8; j++) {
            float L0 = rvL[j*8], L1 = rvL[j*8+1];
            float R0 = rvR[j*8], R1 = rvR[j*8+1];
            #pragma unroll
            for (int i = 0; i < 2; i++) {
                w2a[i][j][0] += lft[i][0]*L0 + rgt[i][0]*R0;
                w2a[i][j][1] += lft[i][0]*L1 + rgt[i][0]*R1;
                w2a[i][j][2] += lft[i][1]*L0 + rgt[i][1]*R0;
                w2a[i][j][3] += lft[i][1]*L1 + rgt[i][1]*R1;
            }
        }
    }

    // Ctx: tf32-rounded + HID-pair-permuted
    const int b = bh / NH, h = bh % NH;
    float inv[2][2];
    #pragma unroll
    for (int i = 0; i < 2; i++)
        #pragma unroll
        for (int hh = 0; hh < 2; hh++)
            inv[i][hh] = 1.f / (lft[i][hh] + rgt[i][hh] + bsum[i][hh]);
    #pragma unroll
    for (int i = 0; i < 2; i++)
        #pragma unroll
        for (int j = 0; j < 8; j++) {
            int cA = h*DHD + j*8 + pA;
            size_t o0 = ((size_t)(b*SEQL + q0 + rlA[i][0]))*HIDD;
            size_t o1 = ((size_t)(b*SEQL + q0 + rlA[i][1]))*HIDD;
            g_Ctx[o0 + cA]     = f2tff((oacc[i][j][0] + w2a[i][j][0]) * inv[i][0]);
            g_Ctx[o0 + cA + 2] = f2tff((oacc[i][j][1] + w2a[i][j][1]) * inv[i][0]);
            g_Ctx[o1 + cA]     = f2tff((oacc[i][j][2] + w2a[i][j][2]) * inv[i][1]);
            g_Ctx[o1 + cA + 2] = f2tff((oacc[i][j][3] + w2a[i][j][3]) * inv[i][1]);
        }
}

// ---------------------------------------------------------------------------
extern "C" void kernel_launch(void* const* d_in, const int* in_sizes, int n_in,
                              void* d_out, int out_size)
{
    const float* query = (const float*)d_in[0];
    const float* key   = (const float*)d_in[1];
    const float* value = (const float*)d_in[2];
    const float* Wq    = (const float*)d_in[3];
    const float* bq    = (const float*)d_in[4];
    const float* Wk    = (const float*)d_in[5];
    const float* bk    = (const float*)d_in[6];
    const float* Wv    = (const float*)d_in[7];
    const float* bv    = (const float*)d_in[8];
    const float* Wo    = (const float*)d_in[9];
    const float* bo    = (const float*)d_in[10];
    const float* rel_k = (const float*)d_in[11];
    const float* rel_v = (const float*)d_in[12];
    float* out = (float*)d_out;

    float *qp, *kp, *vp, *ctx, *xq, *xk, *xv, *wqp, *wkp, *wvp, *wop;
    cudaGetSymbolAddress((void**)&qp, g_Qp);
    cudaGetSymbolAddress((void**)&kp, g_Kp);
    cudaGetSymbolAddress((void**)&vp, g_Vp);
    cudaGetSymbolAddress((void**)&ctx, g_Ctx);
    cudaGetSymbolAddress((void**)&xq, g_Xq);
    cudaGetSymbolAddress((void**)&xk, g_Xk);
    cudaGetSymbolAddress((void**)&xv, g_Xv);
    cudaGetSymbolAddress((void**)&wqp, g_Wqp);
    cudaGetSymbolAddress((void**)&wkp, g_Wkp);
    cudaGetSymbolAddress((void**)&wvp, g_Wvp);
    cudaGetSymbolAddress((void**)&wop, g_Wop);

    dim3 gp((SEQL*BATCH*HIDD/8 + 255)/256, 7);
    preperm<<<gp, 256>>>(query, key, value, Wq, Wk, Wv, Wo,
                         xq, xk, xv, wqp, wkp, wvp, wop);

    dim3 gq(32, 8, 3);
    gemm_qkv<<<gq, 128>>>(bq, bk, bv, qp, kp, vp);

    cudaFuncSetAttribute(attn_tf32, cudaFuncAttributeMaxDynamicSharedMemorySize,
                         ATT_SMEM_BYTES);
    dim3 ga(SEQL / 256, BATCH * NH);
    attn_tf32<<<ga, 256, ATT_SMEM_BYTES>>>(rel_k, rel_v);

    dim3 gg(32, 8);
    gemm_out<<<gg, 128>>>(ctx, wop, bo, out);
}

// round 8
// speedup vs baseline: 1.3281x; 1.3281x over previous
#include <cuda_runtime.h>
#include <cuda_fp16.h>
#include <cstdint>

#define SEQL 2048
#define BATCH 2
#define HIDD 1024
#define NH 16
#define DHD 64
#define NR 101

// fp16 scratch (static __device__ — allocation-free)
__device__ __align__(16) __half g_Qp[BATCH*NH*SEQL*DHD];   // d-permuted
__device__ __align__(16) __half g_Kp[BATCH*NH*SEQL*DHD];   // d-permuted
__device__ __align__(16) __half g_Vp[BATCH*NH*SEQL*DHD];   // plain d
__device__ __align__(16) __half g_Ctx[BATCH*SEQL*HIDD];    // hid-permuted
__device__ __align__(16) __half g_XhQ[SEQL*BATCH*HIDD];
__device__ __align__(16) __half g_XhK[SEQL*BATCH*HIDD];
__device__ __align__(16) __half g_XhV[SEQL*BATCH*HIDD];
__device__ __align__(16) __half g_WhQ[HIDD*HIDD];
__device__ __align__(16) __half g_WhK[HIDD*HIDD];
__device__ __align__(16) __half g_WhV[HIDD*HIDD];
__device__ __align__(16) __half g_WhO[HIDD*HIDD];

__device__ __forceinline__ void mma_f16(float* c, const unsigned* a, const unsigned* b) {
    asm volatile(
        "mma.sync.aligned.m16n8k16.row.col.f32.f16.f16.f32 "
        "{%0,%1,%2,%3}, {%4,%5,%6,%7}, {%8,%9}, {%0,%1,%2,%3};"
        : "+f"(c[0]), "+f"(c[1]), "+f"(c[2]), "+f"(c[3])
        : "r"(a[0]), "r"(a[1]), "r"(a[2]), "r"(a[3]), "r"(b[0]), "r"(b[1]));
}
__device__ __forceinline__ void ldsm_x4_trans(unsigned& r0, unsigned& r1,
                                              unsigned& r2, unsigned& r3, uint32_t addr) {
    asm volatile("ldmatrix.sync.aligned.m8n8.x4.trans.shared.b16 {%0,%1,%2,%3}, [%4];"
                 : "=r"(r0), "=r"(r1), "=r"(r2), "=r"(r3) : "r"(addr));
}
__device__ __forceinline__ uint32_t s2u(const void* p) {
    uint32_t a;
    asm("{ .reg .u64 t; cvta.to.shared.u64 t, %1; cvt.u32.u64 %0, t; }" : "=r"(a) : "l"(p));
    return a;
}

// ---------------------------------------------------------------------------
// Pre-pass: fp32 -> fp16, permuting half2 units within each 16-elem k-group
// as (u0,u4,u1,u5,u2,u6,u3,u7) so mma fragment pairs are address-adjacent.
// ---------------------------------------------------------------------------
__global__ __launch_bounds__(256) void preh(
    const float* __restrict__ q, const float* __restrict__ k, const float* __restrict__ v,
    const float* __restrict__ wq, const float* __restrict__ wk,
    const float* __restrict__ wv, const float* __restrict__ wo)
{
    const float* src; __half* dst; int n16;
    switch (blockIdx.y) {
        case 0: src = q;  dst = g_XhQ; n16 = SEQL*BATCH*HIDD/16; break;
        case 1: src = k;  dst = g_XhK; n16 = SEQL*BATCH*HIDD/16; break;
        case 2: src = v;  dst = g_XhV; n16 = SEQL*BATCH*HIDD/16; break;
        case 3: src = wq; dst = g_WhQ; n16 = HIDD*HIDD/16; break;
        case 4: src = wk; dst = g_WhK; n16 = HIDD*HIDD/16; break;
        case 5: src = wv; dst = g_WhV; n16 = HIDD*HIDD/16; break;
        default: src = wo; dst = g_WhO; n16 = HIDD*HIDD/16; break;
    }
    int g = blockIdx.x * 256 + threadIdx.x;
    if (g >= n16) return;
    const float4* p = (const float4*)(src + (size_t)g * 16);
    float4 x0 = p[0], x1 = p[1], x2 = p[2], x3 = p[3];
    __half2 u0 = __floats2half2_rn(x0.x, x0.y), u1 = __floats2half2_rn(x0.z, x0.w);
    __half2 u2 = __floats2half2_rn(x1.x, x1.y), u3 = __floats2half2_rn(x1.z, x1.w);
    __half2 u4 = __floats2half2_rn(x2.x, x2.y), u5 = __floats2half2_rn(x2.z, x2.w);
    __half2 u6 = __floats2half2_rn(x3.x, x3.y), u7 = __floats2half2_rn(x3.z, x3.w);
    __half2* d = (__half2*)(dst + (size_t)g * 16);
    d[0] = u0; d[1] = u4; d[2] = u1; d[3] = u5;
    d[4] = u2; d[5] = u6; d[6] = u3; d[7] = u7;
}

// ---------------------------------------------------------------------------
// fp16 GEMM m16n8k16: 256 thr, 8 warps (2m x 4n), warp 64x32, tile 128x128,
// BK=16 (one k16 chunk/stage). Stride 24 halfs -> conflict-free LDS.64 frags.
// mode 0: V -> head layout plain d; mode 1: Q/K -> head layout d-permuted;
// mode 2: out-proj fp32 seq-first.
// ---------------------------------------------------------------------------
#define GSTR 24

__device__ __forceinline__ void gemm_body(
    const __half* __restrict__ A, const __half* __restrict__ W,
    const float* __restrict__ bias, void* __restrict__ outv, int mode)
{
    __shared__ __half As[2][128*GSTR];
    __shared__ __half Bs[2][128*GSTR];
    const int tid = threadIdx.x, lane = tid & 31, warp = tid >> 5;
    const int grp = lane >> 2, l4 = lane & 3;
    const int wm = (warp >> 2) * 64, wn = (warp & 3) * 32;
    const int m0 = blockIdx.x * 128, n0 = blockIdx.y * 128;
    float acc[4][4][4];
    #pragma unroll
    for (int i = 0; i < 4; i++)
        #pragma unroll
        for (int j = 0; j < 4; j++)
            #pragma unroll
            for (int r = 0; r < 4; r++) acc[i][j][r] = 0.f;

    const int frow = tid & 127, part = tid >> 7;
    const __half *apt, *bpt;
    {
        int m = m0 + frow;
        if (mode < 2) { int b = m >> 11, l = m & 2047; apt = A + (size_t)(l*BATCH+b)*HIDD + part*8; }
        else          { apt = A + (size_t)m*HIDD + part*8; }
        bpt = W + (size_t)(n0 + frow)*HIDD + part*8;
    }
    uint4 va = *(const uint4*)apt;
    uint4 vb = *(const uint4*)bpt;

    auto sts = [&](int buf) {
        *(uint4*)&As[buf][frow*GSTR + part*8] = va;
        *(uint4*)&Bs[buf][frow*GSTR + part*8] = vb;
    };
    sts(0);
    __syncthreads();

    int cur = 0;
    for (int kt = 0; kt < 64; kt++) {
        if (kt + 1 < 64) {
            va = *(const uint4*)(apt + (kt+1)*16);
            vb = *(const uint4*)(bpt + (kt+1)*16);
        }
        const __half* as = As[cur]; const __half* bs = Bs[cur];
        unsigned af[4][4], bf[4][2];
        #pragma unroll
        for (int i = 0; i < 4; i++) {
            int rr = wm + i*16 + grp;
            uint2 t0 = *(const uint2*)&as[rr*GSTR + 4*l4];
            uint2 t1 = *(const uint2*)&as[(rr+8)*GSTR + 4*l4];
            af[i][0] = t0.x; af[i][1] = t1.x; af[i][2] = t0.y; af[i][3] = t1.y;
        }
        #pragma unroll
        for (int j = 0; j < 4; j++) {
            int nn = wn + j*8 + grp;
            uint2 tb = *(const uint2*)&bs[nn*GSTR + 4*l4];
            bf[j][0] = tb.x; bf[j][1] = tb.y;
        }
        #pragma unroll
        for (int i = 0; i < 4; i++)
            #pragma unroll
            for (int j = 0; j < 4; j++)
                mma_f16(acc[i][j], af[i], bf[j]);
        if (kt + 1 < 64) sts(cur ^ 1);
        __syncthreads();
        cur ^= 1;
    }

    #pragma unroll
    for (int i = 0; i < 4; i++) {
        #pragma unroll
        for (int j = 0; j < 4; j++) {
            int col = n0 + wn + j*8 + l4*2;
            float b0v = bias[col], b1v = bias[col+1];
            #pragma unroll
            for (int pr = 0; pr < 2; pr++) {
                int rw = m0 + wm + i*16 + grp + pr*8;
                int b = rw >> 11, l = rw & 2047;
                float v0 = acc[i][j][pr*2+0] + b0v;
                float v1 = acc[i][j][pr*2+1] + b1v;
                if (mode == 2) {
                    float* p = (float*)outv + (size_t)(l*BATCH+b)*HIDD + col;
                    p[0] = v0; p[1] = v1;
                } else {
                    int h = col >> 6;
                    __half* p = (__half*)outv + ((size_t)(b*NH+h)*SEQL + l)*DHD;
                    int d;
                    if (mode == 1) {
                        int g16 = (col & 63) >> 4;
                        int pp = (j & 1) ? 2*l4 + 1 : 2*l4;
                        d = g16*16 + 2*pp;
                    } else d = col & 63;
                    *(__half2*)(p + d) = __floats2half2_rn(v0, v1);
                }
            }
        }
    }
}

__global__ __launch_bounds__(256, 2) void gemm_qkv(
    const float* __restrict__ bq, const float* __restrict__ bk, const float* __restrict__ bv)
{
    if (blockIdx.z == 0)      gemm_body(g_XhQ, g_WhQ, bq, g_Qp, 1);
    else if (blockIdx.z == 1) gemm_body(g_XhK, g_WhK, bk, g_Kp, 1);
    else                      gemm_body(g_XhV, g_WhV, bv, g_Vp, 0);
}

__global__ __launch_bounds__(256, 2) void gemm_out_h(
    const float* __restrict__ bo, float* __restrict__ out)
{
    gemm_body(g_Ctx, g_WhO, bo, out, 2);
}

// ---------------------------------------------------------------------------
// fp16 flash relative-attention: 128 thr (4 warps), q-tile 64, k-tiles 64,
// one-pass (bounded scores). Q/K d-permuted (LDS.64 frags), P stored
// kl-permuted, V plain + ldmatrix.trans B-frags. Band + QD fp16 in smem.
// ---------------------------------------------------------------------------
#define AQS 80
#define AVS 72
#define OFFQ 0            // Q [64][80]; alias band [64][100] fp16
#define OFFK 6400         // relk [104][80] / K tile [64][80] / P / rel_v [101][64]
#define OFFV 14720        // V [64][72]
#define OFFQD 19328       // QD [64][104] fp16
#define ATT_SMEM_BYTES (25984*2)
#define C8 0.18033688011112042f   // 0.125 * log2(e)

__global__ __launch_bounds__(128, 4) void attn_h(
    const float* __restrict__ rel_k, const float* __restrict__ rel_v)
{
    extern __shared__ __half sm16[];
    const uint32_t smb = s2u(sm16);
    __half* qdp = sm16 + OFFQD;
    __half* pbd = sm16 + OFFQ;
    const int tid = threadIdx.x;
    const int lane = tid & 31, w = tid >> 5;
    const int grp = lane >> 2, l4 = lane & 3;
    const int bh = blockIdx.y;
    const int q0 = blockIdx.x * 64;
    const size_t base = (size_t)bh * SEQL * DHD;
    const int rl0 = w*16 + grp;

    // Q tile fill (fp16, d-permuted): straight uint4 copy
    #pragma unroll
    for (int s = 0; s < 4; s++) {
        int idx = tid + s*128; int r = idx >> 3, c8 = (idx & 7)*8;
        *(uint4*)&sm16[OFFQ + r*AQS + c8] =
            *(const uint4*)(g_Qp + base + (size_t)(q0+r)*DHD + c8);
    }
    // rel_k rows 0..103 (zero-pad), fp32 -> fp16 permuted scatter
    #pragma unroll
    for (int s = 0; s < 13; s++) {
        int i = tid + s*128;
        if (i < 104*16) {
            int r = i >> 4, c4 = (i & 15)*4;
            float4 v = make_float4(0.f,0.f,0.f,0.f);
            if (r < NR) v = *(const float4*)(rel_k + r*DHD + c4);
            int g16 = c4 & ~15;
            int u0 = (c4 & 15) >> 1;          // 0,2,4,6
            int p0 = (u0 < 4) ? 2*u0 : 2*(u0-4)+1;
            int p1 = (u0+1 < 4) ? 2*(u0+1) : 2*(u0+1-4)+1;
            __half2* dst = (__half2*)&sm16[OFFK + r*AQS + g16];
            dst[p0] = __floats2half2_rn(v.x, v.y);
            dst[p1] = __floats2half2_rn(v.z, v.w);
        }
    }
    __syncthreads();

    // persistent Q fragments
    unsigned qf[4][4];
    #pragma unroll
    for (int c = 0; c < 4; c++) {
        uint2 t0 = *(const uint2*)&sm16[OFFQ + rl0*AQS + c*16 + 4*l4];
        uint2 t1 = *(const uint2*)&sm16[OFFQ + (rl0+8)*AQS + c*16 + 4*l4];
        qf[c][0] = t0.x; qf[c][1] = t1.x; qf[c][2] = t0.y; qf[c][3] = t1.y;
    }
    // qdot = Q . rel_k -> fp16 QD table
    #pragma unroll
    for (int j = 0; j < 13; j++) {
        float c4a[4] = {0.f, 0.f, 0.f, 0.f};
        #pragma unroll
        for (int c = 0; c < 4; c++) {
            uint2 tb = *(const uint2*)&sm16[OFFK + (j*8+grp)*AQS + c*16 + 4*l4];
            unsigned bf2[2] = {tb.x, tb.y};
            mma_f16(c4a, qf[c], bf2);
        }
        int col = j*8 + l4*2;
        *(__half2*)&qdp[rl0*104 + col]     = __floats2half2_rn(c4a[0], c4a[1]);
        *(__half2*)&qdp[(rl0+8)*104 + col] = __floats2half2_rn(c4a[2], c4a[3]);
    }
    __syncthreads();

    // zero band (aliases Q region; 64*100 halfs = 3200 words)
    {
        unsigned* bw = (unsigned*)pbd;
        #pragma unroll
        for (int s = 0; s < 25; s++) bw[tid + s*128] = 0u;
    }
    float qlC[2], qrC[2];
    #pragma unroll
    for (int hh = 0; hh < 2; hh++) {
        qlC[hh] = __half2float(qdp[(rl0+hh*8)*104 + 0])   * C8;
        qrC[hh] = __half2float(qdp[(rl0+hh*8)*104 + 100]) * C8;
    }
    __syncthreads();

    float oacc[8][4];
    #pragma unroll
    for (int j = 0; j < 8; j++)
        #pragma unroll
        for (int r = 0; r < 4; r++) oacc[j][r] = 0.f;
    float lft[2] = {0.f, 0.f}, rgt[2] = {0.f, 0.f};

    uint4 kreg[4], vreg[4];
    #pragma unroll
    for (int s = 0; s < 4; s++) {
        int idx = tid + s*128; int r = idx >> 3, c8 = (idx & 7)*8;
        kreg[s] = *(const uint4*)(g_Kp + base + (size_t)r*DHD + c8);
        vreg[s] = *(const uint4*)(g_Vp + base + (size_t)r*DHD + c8);
    }

    for (int kt = 0; kt < 32; kt++) {
        const int k0 = kt * 64;
        #pragma unroll
        for (int s = 0; s < 4; s++) {
            int idx = tid + s*128; int r = idx >> 3, c8 = (idx & 7)*8;
            *(uint4*)&sm16[OFFK + r*AQS + c8] = kreg[s];
            *(uint4*)&sm16[OFFV + r*AVS + c8] = vreg[s];
        }
        __syncthreads();
        if (kt + 1 < 32) {
            #pragma unroll
            for (int s = 0; s < 4; s++) {
                int idx = tid + s*128; int r = idx >> 3, c8 = (idx & 7)*8;
                size_t g = base + (size_t)(k0 + 64 + r)*DHD + c8;
                kreg[s] = *(const uint4*)(g_Kp + g);
                vreg[s] = *(const uint4*)(g_Vp + g);
            }
        }

        // S = Q K^T
        float sfr[8][4];
        #pragma unroll
        for (int j = 0; j < 8; j++) {
            sfr[j][0]=sfr[j][1]=sfr[j][2]=sfr[j][3]=0.f;
            #pragma unroll
            for (int c = 0; c < 4; c++) {
                uint2 tb = *(const uint2*)&sm16[OFFK + (j*8+grp)*AQS + c*16 + 4*l4];
                unsigned bf2[2] = {tb.x, tb.y};
                mma_f16(sfr[j], qf[c], bf2);
            }
        }
        __syncthreads();   // all warps done reading K before P overwrites

        const int dq = k0 - q0;
        if (dq == -64 || dq == 0 || dq == 64) {
            #pragma unroll
            for (int j = 0; j < 8; j++) {
                #pragma unroll
                for (int hh = 0; hh < 2; hh++) {
                    int rl = rl0 + hh*8;
                    int col = j*8 + l4*2;
                    int dlt = k0 + col - (q0 + rl);
                    int ix0 = min(max(dlt, -50), 50) + 50;
                    int ix1 = min(max(dlt+1, -50), 50) + 50;
                    float qd0 = __half2float(qdp[rl*104 + ix0]);
                    float qd1 = __half2float(qdp[rl*104 + ix1]);
                    float p0 = exp2f((sfr[j][hh*2+0] + qd0) * C8);
                    float p1 = exp2f((sfr[j][hh*2+1] + qd1) * C8);
                    if (dlt <= -50)     lft[hh] += p0;
                    else if (dlt >= 50) rgt[hh] += p0;
                    else pbd[rl*100 + dlt + 49] = __float2half(p0);
                    if (dlt+1 <= -50)     lft[hh] += p1;
                    else if (dlt+1 >= 50) rgt[hh] += p1;
                    else pbd[rl*100 + dlt + 50] = __float2half(p1);
                    int off = rl*AQS + (j>>1)*16 + ((j&1) ? 4*l4+2 : 4*l4);
                    *(__half2*)&sm16[OFFK + off] = __floats2half2_rn(p0, p1);
                }
            }
        } else {
            const bool leftT = dq < 0;
            const float qc0 = leftT ? qlC[0] : qrC[0];
            const float qc1 = leftT ? qlC[1] : qrC[1];
            float ts[2] = {0.f, 0.f};
            #pragma unroll
            for (int j = 0; j < 8; j++) {
                float p0 = exp2f(fmaf(sfr[j][0], C8, qc0));
                float p1 = exp2f(fmaf(sfr[j][1], C8, qc0));
                float p2 = exp2f(fmaf(sfr[j][2], C8, qc1));
                float p3 = exp2f(fmaf(sfr[j][3], C8, qc1));
                ts[0] += p0 + p1;
                ts[1] += p2 + p3;
                int po = (j>>1)*16 + ((j&1) ? 4*l4+2 : 4*l4);
                *(__half2*)&sm16[OFFK + rl0*AQS + po]     = __floats2half2_rn(p0, p1);
                *(__half2*)&sm16[OFFK + (rl0+8)*AQS + po] = __floats2half2_rn(p2, p3);
            }
            if (leftT) { lft[0] += ts[0]; lft[1] += ts[1]; }
            else       { rgt[0] += ts[0]; rgt[1] += ts[1]; }
        }
        __syncwarp();

        // O += P V : A-frags from permuted P (LDS.64), B via ldmatrix.trans
        #pragma unroll
        for (int c = 0; c < 4; c++) {
            uint2 t0 = *(const uint2*)&sm16[OFFK + rl0*AQS + c*16 + 4*l4];
            uint2 t1 = *(const uint2*)&sm16[OFFK + (rl0+8)*AQS + c*16 + 4*l4];
            unsigned af[4] = {t0.x, t1.x, t0.y, t1.y};
            #pragma unroll
            for (int jj = 0; jj < 8; jj += 2) {
                unsigned r0, r1, r2, r3;
                int mm = lane >> 3, rs = lane & 7;
                uint32_t ad = smb + 2u*(OFFV + (c*16 + (mm&1)*8 + rs)*AVS + (jj + (mm>>1))*8);
                ldsm_x4_trans(r0, r1, r2, r3, ad);
                unsigned b0[2] = {r0, r1}, b1[2] = {r2, r3};
                mma_f16(oacc[jj],   af, b0);
                mma_f16(oacc[jj+1], af, b1);
            }
        }
        __syncthreads();
    }

    // quad-reduce clip masses
    #pragma unroll
    for (int hh = 0; hh < 2; hh++) {
        lft[hh] += __shfl_xor_sync(0xffffffffu, lft[hh], 1);
        lft[hh] += __shfl_xor_sync(0xffffffffu, lft[hh], 2);
        rgt[hh] += __shfl_xor_sync(0xffffffffu, rgt[hh], 1);
        rgt[hh] += __shfl_xor_sync(0xffffffffu, rgt[hh], 2);
    }

    // rel_v fp16 plain [101][64] into dead K region
    #pragma unroll
    for (int s = 0; s < 13; s++) {
        int i = tid + s*128;
        if (i < NR*16) {
            int r = i >> 4, c4 = (i & 15)*4;
            float4 v = *(const float4*)(rel_v + r*DHD + c4);
            __half2* dst = (__half2*)&sm16[OFFK + r*64 + c4];
            dst[0] = __floats2half2_rn(v.x, v.y);
            dst[1] = __floats2half2_rn(v.z, v.w);
        }
    }
    __syncthreads();

    float w2a[8][4];
    #pragma unroll
    for (int j = 0; j < 8; j++)
        #pragma unroll
        for (int r = 0; r < 4; r++) w2a[j][r] = 0.f;
    float bs0 = 0.f, bs1 = 0.f;
    for (int bnd = 0; bnd < 99; bnd++) {
        float pb0 = __half2float(pbd[rl0*100 + bnd]);
        float pb1 = __half2float(pbd[(rl0+8)*100 + bnd]);
        bs0 += pb0; bs1 += pb1;
        const __half* rv = &sm16[OFFK + (bnd+1)*64 + l4*2];
        #pragma unroll
        for (int j = 0; j < 8; j++) {
            float2 rr = __half22float2(*(const __half2*)&rv[j*8]);
            w2a[j][0] += pb0*rr.x; w2a[j][1] += pb0*rr.y;
            w2a[j][2] += pb1*rr.x; w2a[j][3] += pb1*rr.y;
        }
    }
    {
        const __half* rvL = &sm16[OFFK + 0*64   + l4*2];
        const __half* rvR = &sm16[OFFK + 100*64 + l4*2];
        #pragma unroll
        for (int j = 0; j < 8; j++) {
            float2 L = __half22float2(*(const __half2*)&rvL[j*8]);
            float2 R = __half22float2(*(const __half2*)&rvR[j*8]);
            w2a[j][0] += lft[0]*L.x + rgt[0]*R.x;
            w2a[j][1] += lft[0]*L.y + rgt[0]*R.y;
            w2a[j][2] += lft[1]*L.x + rgt[1]*R.x;
            w2a[j][3] += lft[1]*L.y + rgt[1]*R.y;
        }
    }

    // Ctx: fp16 hid-permuted for gemm_out fast path
    const int b = bh / NH, h = bh % NH;
    const float inv0 = 1.f / (lft[0] + rgt[0] + bs0);
    const float inv1 = 1.f / (lft[1] + rgt[1] + bs1);
    #pragma unroll
    for (int j = 0; j < 8; j++) {
        int pp = (j & 1) ? 2*l4 + 1 : 2*l4;
        int dcol = (j>>1)*16 + 2*pp;
        size_t o0 = ((size_t)(b*SEQL + q0 + rl0))*HIDD + h*DHD + dcol;
        size_t o1 = ((size_t)(b*SEQL + q0 + rl0 + 8))*HIDD + h*DHD + dcol;
        *(__half2*)&g_Ctx[o0] = __floats2half2_rn((oacc[j][0] + w2a[j][0]) * inv0,
                                                  (oacc[j][1] + w2a[j][1]) * inv0);
        *(__half2*)&g_Ctx[o1] = __floats2half2_rn((oacc[j][2] + w2a[j][2]) * inv1,
                                                  (oacc[j][3] + w2a[j][3]) * inv1);
    }
}

// ---------------------------------------------------------------------------
extern "C" void kernel_launch(void* const* d_in, const int* in_sizes, int n_in,
                              void* d_out, int out_size)
{
    const float* query = (const float*)d_in[0];
    const float* key   = (const float*)d_in[1];
    const float* value = (const float*)d_in[2];
    const float* Wq    = (const float*)d_in[3];
    const float* bq    = (const float*)d_in[4];
    const float* Wk    = (const float*)d_in[5];
    const float* bk    = (const float*)d_in[6];
    const float* Wv    = (const float*)d_in[7];
    const float* bv    = (const float*)d_in[8];
    const float* Wo    = (const float*)d_in[9];
    const float* bo    = (const float*)d_in[10];
    const float* rel_k = (const float*)d_in[11];
    const float* rel_v = (const float*)d_in[12];
    float* out = (float*)d_out;

    dim3 gp((SEQL*BATCH*HIDD/16 + 255)/256, 7);
    preh<<<gp, 256>>>(query, key, value, Wq, Wk, Wv, Wo);

    dim3 gq(32, 8, 3);
    gemm_qkv<<<gq, 256>>>(bq, bk, bv);

    cudaFuncSetAttribute(attn_h, cudaFuncAttributeMaxDynamicSharedMemorySize,
                         ATT_SMEM_BYTES);
    dim3 ga(SEQL / 64, BATCH * NH);
    attn_h<<<ga, 128, ATT_SMEM_BYTES>>>(rel_k, rel_v);

    dim3 gg(32, 8);
    gemm_out_h<<<gg, 256>>>(bo, out);
}

// round 9
// speedup vs baseline: 1.4355x; 1.0809x over previous
#include <cuda_runtime.h>
#include <cuda_fp16.h>
#include <cstdint>

#define SEQL 2048
#define BATCH 2
#define HIDD 1024
#define NH 16
#define DHD 64
#define NR 101

// fp16 scratch (static __device__ — allocation-free)
__device__ __align__(16) __half g_Qp[BATCH*NH*SEQL*DHD];   // d-permuted
__device__ __align__(16) __half g_Kp[BATCH*NH*SEQL*DHD];   // d-permuted
__device__ __align__(16) __half g_Vp[BATCH*NH*SEQL*DHD];   // plain d
__device__ __align__(16) __half g_Ctx[BATCH*SEQL*HIDD];    // hid-permuted
__device__ __align__(16) __half g_XhQ[SEQL*BATCH*HIDD];
__device__ __align__(16) __half g_XhK[SEQL*BATCH*HIDD];
__device__ __align__(16) __half g_XhV[SEQL*BATCH*HIDD];
__device__ __align__(16) __half g_WhQ[HIDD*HIDD];
__device__ __align__(16) __half g_WhK[HIDD*HIDD];
__device__ __align__(16) __half g_WhV[HIDD*HIDD];
__device__ __align__(16) __half g_WhO[HIDD*HIDD];

__device__ __forceinline__ void mma_f16(float* c, const unsigned* a, const unsigned* b) {
    asm volatile(
        "mma.sync.aligned.m16n8k16.row.col.f32.f16.f16.f32 "
        "{%0,%1,%2,%3}, {%4,%5,%6,%7}, {%8,%9}, {%0,%1,%2,%3};"
        : "+f"(c[0]), "+f"(c[1]), "+f"(c[2]), "+f"(c[3])
        : "r"(a[0]), "r"(a[1]), "r"(a[2]), "r"(a[3]), "r"(b[0]), "r"(b[1]));
}
__device__ __forceinline__ void ldsm_x4_trans(unsigned& r0, unsigned& r1,
                                              unsigned& r2, unsigned& r3, uint32_t addr) {
    asm volatile("ldmatrix.sync.aligned.m8n8.x4.trans.shared.b16 {%0,%1,%2,%3}, [%4];"
                 : "=r"(r0), "=r"(r1), "=r"(r2), "=r"(r3) : "r"(addr));
}
__device__ __forceinline__ uint32_t s2u(const void* p) {
    uint32_t a;
    asm("{ .reg .u64 t; cvta.to.shared.u64 t, %1; cvt.u32.u64 %0, t; }" : "=r"(a) : "l"(p));
    return a;
}

// ---------------------------------------------------------------------------
// Pre-pass: fp32 -> fp16, permuting half2 units within each 16-elem k-group
// as (u0,u4,u1,u5,u2,u6,u3,u7) so mma fragment pairs are address-adjacent.
// ---------------------------------------------------------------------------
__global__ __launch_bounds__(256) void preh(
    const float* __restrict__ q, const float* __restrict__ k, const float* __restrict__ v,
    const float* __restrict__ wq, const float* __restrict__ wk,
    const float* __restrict__ wv, const float* __restrict__ wo)
{
    const float* src; __half* dst; int n16;
    switch (blockIdx.y) {
        case 0: src = q;  dst = g_XhQ; n16 = SEQL*BATCH*HIDD/16; break;
        case 1: src = k;  dst = g_XhK; n16 = SEQL*BATCH*HIDD/16; break;
        case 2: src = v;  dst = g_XhV; n16 = SEQL*BATCH*HIDD/16; break;
        case 3: src = wq; dst = g_WhQ; n16 = HIDD*HIDD/16; break;
        case 4: src = wk; dst = g_WhK; n16 = HIDD*HIDD/16; break;
        case 5: src = wv; dst = g_WhV; n16 = HIDD*HIDD/16; break;
        default: src = wo; dst = g_WhO; n16 = HIDD*HIDD/16; break;
    }
    int g = blockIdx.x * 256 + threadIdx.x;
    if (g >= n16) return;
    const float4* p = (const float4*)(src + (size_t)g * 16);
    float4 x0 = p[0], x1 = p[1], x2 = p[2], x3 = p[3];
    __half2 u0 = __floats2half2_rn(x0.x, x0.y), u1 = __floats2half2_rn(x0.z, x0.w);
    __half2 u2 = __floats2half2_rn(x1.x, x1.y), u3 = __floats2half2_rn(x1.z, x1.w);
    __half2 u4 = __floats2half2_rn(x2.x, x2.y), u5 = __floats2half2_rn(x2.z, x2.w);
    __half2 u6 = __floats2half2_rn(x3.x, x3.y), u7 = __floats2half2_rn(x3.z, x3.w);
    __half2* d = (__half2*)(dst + (size_t)g * 16);
    d[0] = u0; d[1] = u4; d[2] = u1; d[3] = u5;
    d[4] = u2; d[5] = u6; d[6] = u3; d[7] = u7;
}

// ---------------------------------------------------------------------------
// fp16 GEMM m16n8k16: 128 thr, 4 warps (2m x 2n), warp 64x64, tile 128x128,
// BK=16 double-buffered. Stride 24 halfs. A-frags reused over 8 n-tiles.
// mode 0: V -> head layout plain d; mode 1: Q/K -> head layout d-permuted;
// mode 2: out-proj fp32 seq-first.
// ---------------------------------------------------------------------------
#define GSTR 24

__device__ __forceinline__ void gemm_body(
    const __half* __restrict__ A, const __half* __restrict__ W,
    const float* __restrict__ bias, void* __restrict__ outv, int mode)
{
    __shared__ __half As[2][128*GSTR];
    __shared__ __half Bs[2][128*GSTR];
    const int tid = threadIdx.x, lane = tid & 31, warp = tid >> 5;
    const int grp = lane >> 2, l4 = lane & 3;
    const int wm = (warp >> 1) * 64, wn = (warp & 1) * 64;
    const int m0 = blockIdx.x * 128, n0 = blockIdx.y * 128;
    float acc[4][8][4];
    #pragma unroll
    for (int i = 0; i < 4; i++)
        #pragma unroll
        for (int j = 0; j < 8; j++)
            #pragma unroll
            for (int r = 0; r < 4; r++) acc[i][j][r] = 0.f;

    const __half *apt, *bpt;
    {
        int m = m0 + tid;
        if (mode < 2) { int b = m >> 11, l = m & 2047; apt = A + (size_t)(l*BATCH+b)*HIDD; }
        else          { apt = A + (size_t)m*HIDD; }
        bpt = W + (size_t)(n0 + tid)*HIDD;
    }
    uint4 va0 = *(const uint4*)apt,       va1 = *(const uint4*)(apt + 8);
    uint4 vb0 = *(const uint4*)bpt,       vb1 = *(const uint4*)(bpt + 8);

    auto sts = [&](int buf) {
        *(uint4*)&As[buf][tid*GSTR]     = va0;
        *(uint4*)&As[buf][tid*GSTR + 8] = va1;
        *(uint4*)&Bs[buf][tid*GSTR]     = vb0;
        *(uint4*)&Bs[buf][tid*GSTR + 8] = vb1;
    };
    sts(0);
    __syncthreads();

    int cur = 0;
    for (int kt = 0; kt < 64; kt++) {
        if (kt + 1 < 64) {
            const __half* ap = apt + (kt+1)*16;
            const __half* bp = bpt + (kt+1)*16;
            va0 = *(const uint4*)ap; va1 = *(const uint4*)(ap + 8);
            vb0 = *(const uint4*)bp; vb1 = *(const uint4*)(bp + 8);
        }
        const __half* as = As[cur]; const __half* bs = Bs[cur];
        unsigned af[4][4], bf[8][2];
        #pragma unroll
        for (int i = 0; i < 4; i++) {
            int rr = wm + i*16 + grp;
            uint2 t0 = *(const uint2*)&as[rr*GSTR + 4*l4];
            uint2 t1 = *(const uint2*)&as[(rr+8)*GSTR + 4*l4];
            af[i][0] = t0.x; af[i][1] = t1.x; af[i][2] = t0.y; af[i][3] = t1.y;
        }
        #pragma unroll
        for (int j = 0; j < 8; j++) {
            int nn = wn + j*8 + grp;
            uint2 tb = *(const uint2*)&bs[nn*GSTR + 4*l4];
            bf[j][0] = tb.x; bf[j][1] = tb.y;
        }
        #pragma unroll
        for (int i = 0; i < 4; i++)
            #pragma unroll
            for (int j = 0; j < 8; j++)
                mma_f16(acc[i][j], af[i], bf[j]);
        if (kt + 1 < 64) sts(cur ^ 1);
        __syncthreads();
        cur ^= 1;
    }

    #pragma unroll
    for (int i = 0; i < 4; i++) {
        #pragma unroll
        for (int j = 0; j < 8; j++) {
            int col = n0 + wn + j*8 + l4*2;
            float b0v = bias[col], b1v = bias[col+1];
            #pragma unroll
            for (int pr = 0; pr < 2; pr++) {
                int rw = m0 + wm + i*16 + grp + pr*8;
                int b = rw >> 11, l = rw & 2047;
                float v0 = acc[i][j][pr*2+0] + b0v;
                float v1 = acc[i][j][pr*2+1] + b1v;
                if (mode == 2) {
                    float* p = (float*)outv + (size_t)(l*BATCH+b)*HIDD + col;
                    p[0] = v0; p[1] = v1;
                } else {
                    int h = col >> 6;
                    __half* p = (__half*)outv + ((size_t)(b*NH+h)*SEQL + l)*DHD;
                    int d;
                    if (mode == 1) {
                        int g16 = (col & 63) >> 4;
                        int pp = (j & 1) ? 2*l4 + 1 : 2*l4;
                        d = g16*16 + 2*pp;
                    } else d = col & 63;
                    *(__half2*)(p + d) = __floats2half2_rn(v0, v1);
                }
            }
        }
    }
}

__global__ __launch_bounds__(128, 2) void gemm_qkv(
    const float* __restrict__ bq, const float* __restrict__ bk, const float* __restrict__ bv)
{
    if (blockIdx.z == 0)      gemm_body(g_XhQ, g_WhQ, bq, g_Qp, 1);
    else if (blockIdx.z == 1) gemm_body(g_XhK, g_WhK, bk, g_Kp, 1);
    else                      gemm_body(g_XhV, g_WhV, bv, g_Vp, 0);
}

__global__ __launch_bounds__(128, 2) void gemm_out_h(
    const float* __restrict__ bo, float* __restrict__ out)
{
    gemm_body(g_Ctx, g_WhO, bo, out, 2);
}

// ---------------------------------------------------------------------------
// fp16 flash relative-attention: 128 thr (4 warps), q-tile 128 (warp: 32 rows,
// 2 row-groups), k-tiles 64, one-pass. P lives in dead Q region (no mid sync).
// K frags + ldsm'd V frags amortized over 2 row-groups. 2 CTAs/SM.
// ---------------------------------------------------------------------------
#define AQS 80
#define AVS 72
#define OFFQ 0              // Q [128][80]; later P [128][80]
#define OFFK 10240          // relk [104][80] / K tile [64][80] / relv [101][64]
#define OFFV 18560          // V [64][72]
#define OFFQD 23168         // QD [128][104] fp16
#define OFFBD 36480         // band [128][100] fp16
#define ATT_SMEM_BYTES (49280*2)
#define C8 0.18033688011112042f   // 0.125 * log2(e)

__global__ __launch_bounds__(128, 2) void attn_h(
    const float* __restrict__ rel_k, const float* __restrict__ rel_v)
{
    extern __shared__ __half sm16[];
    const uint32_t smb = s2u(sm16);
    __half* qdp = sm16 + OFFQD;
    __half* pbd = sm16 + OFFBD;
    const int tid = threadIdx.x;
    const int lane = tid & 31, w = tid >> 5;
    const int grp = lane >> 2, l4 = lane & 3;
    const int bh = blockIdx.y;
    const int q0 = blockIdx.x * 128;
    const size_t base = (size_t)bh * SEQL * DHD;
    int rl[2][2];
    #pragma unroll
    for (int i = 0; i < 2; i++)
        #pragma unroll
        for (int hh = 0; hh < 2; hh++) rl[i][hh] = w*32 + i*16 + hh*8 + grp;

    // Q tile fill (fp16, d-permuted): 128 rows
    #pragma unroll
    for (int s = 0; s < 8; s++) {
        int idx = tid + s*128; int r = idx >> 3, c8 = (idx & 7)*8;
        *(uint4*)&sm16[OFFQ + r*AQS + c8] =
            *(const uint4*)(g_Qp + base + (size_t)(q0+r)*DHD + c8);
    }
    // rel_k rows 0..103 (zero-pad), fp32 -> fp16 permuted scatter
    #pragma unroll
    for (int s = 0; s < 13; s++) {
        int i = tid + s*128;
        if (i < 104*16) {
            int r = i >> 4, c4 = (i & 15)*4;
            float4 v = make_float4(0.f,0.f,0.f,0.f);
            if (r < NR) v = *(const float4*)(rel_k + r*DHD + c4);
            int g16 = c4 & ~15;
            int u0 = (c4 & 15) >> 1;          // 0,2,4,6
            int p0 = (u0 < 4) ? 2*u0 : 2*(u0-4)+1;
            int p1 = (u0+1 < 4) ? 2*(u0+1) : 2*(u0+1-4)+1;
            __half2* dst = (__half2*)&sm16[OFFK + r*AQS + g16];
            dst[p0] = __floats2half2_rn(v.x, v.y);
            dst[p1] = __floats2half2_rn(v.z, v.w);
        }
    }
    __syncthreads();

    // persistent Q fragments (2 row-groups)
    unsigned qf[2][4][4];
    #pragma unroll
    for (int i = 0; i < 2; i++)
        #pragma unroll
        for (int c = 0; c < 4; c++) {
            uint2 t0 = *(const uint2*)&sm16[OFFQ + rl[i][0]*AQS + c*16 + 4*l4];
            uint2 t1 = *(const uint2*)&sm16[OFFQ + rl[i][1]*AQS + c*16 + 4*l4];
            qf[i][c][0] = t0.x; qf[i][c][1] = t1.x;
            qf[i][c][2] = t0.y; qf[i][c][3] = t1.y;
        }
    // qdot = Q . rel_k -> fp16 QD table [128][104]
    #pragma unroll
    for (int j = 0; j < 13; j++) {
        float c4a[2][4];
        #pragma unroll
        for (int i = 0; i < 2; i++)
            #pragma unroll
            for (int r = 0; r < 4; r++) c4a[i][r] = 0.f;
        #pragma unroll
        for (int c = 0; c < 4; c++) {
            uint2 tb = *(const uint2*)&sm16[OFFK + (j*8+grp)*AQS + c*16 + 4*l4];
            unsigned bf2[2] = {tb.x, tb.y};
            mma_f16(c4a[0], qf[0][c], bf2);
            mma_f16(c4a[1], qf[1][c], bf2);
        }
        int col = j*8 + l4*2;
        #pragma unroll
        for (int i = 0; i < 2; i++) {
            *(__half2*)&qdp[rl[i][0]*104 + col] = __floats2half2_rn(c4a[i][0], c4a[i][1]);
            *(__half2*)&qdp[rl[i][1]*104 + col] = __floats2half2_rn(c4a[i][2], c4a[i][3]);
        }
    }
    __syncthreads();

    // zero band [128][100] halfs = 6400 words
    {
        unsigned* bw = (unsigned*)pbd;
        #pragma unroll
        for (int s = 0; s < 50; s++) bw[tid + s*128] = 0u;
    }
    float qlC[2][2], qrC[2][2];
    #pragma unroll
    for (int i = 0; i < 2; i++)
        #pragma unroll
        for (int hh = 0; hh < 2; hh++) {
            qlC[i][hh] = __half2float(qdp[rl[i][hh]*104 + 0])   * C8;
            qrC[i][hh] = __half2float(qdp[rl[i][hh]*104 + 100]) * C8;
        }
    __syncthreads();

    float oacc[2][8][4];
    #pragma unroll
    for (int i = 0; i < 2; i++)
        #pragma unroll
        for (int j = 0; j < 8; j++)
            #pragma unroll
            for (int r = 0; r < 4; r++) oacc[i][j][r] = 0.f;
    float lft[2][2] = {{0.f,0.f},{0.f,0.f}}, rgt[2][2] = {{0.f,0.f},{0.f,0.f}};

    uint4 kreg[4], vreg[4];
    #pragma unroll
    for (int s = 0; s < 4; s++) {
        int idx = tid + s*128; int r = idx >> 3, c8 = (idx & 7)*8;
        kreg[s] = *(const uint4*)(g_Kp + base + (size_t)r*DHD + c8);
        vreg[s] = *(const uint4*)(g_Vp + base + (size_t)r*DHD + c8);
    }

    for (int kt = 0; kt < 32; kt++) {
        const int k0 = kt * 64;
        #pragma unroll
        for (int s = 0; s < 4; s++) {
            int idx = tid + s*128; int r = idx >> 3, c8 = (idx & 7)*8;
            *(uint4*)&sm16[OFFK + r*AQS + c8] = kreg[s];
            *(uint4*)&sm16[OFFV + r*AVS + c8] = vreg[s];
        }
        __syncthreads();
        if (kt + 1 < 32) {
            #pragma unroll
            for (int s = 0; s < 4; s++) {
                int idx = tid + s*128; int r = idx >> 3, c8 = (idx & 7)*8;
                size_t g = base + (size_t)(k0 + 64 + r)*DHD + c8;
                kreg[s] = *(const uint4*)(g_Kp + g);
                vreg[s] = *(const uint4*)(g_Vp + g);
            }
        }

        const int dq = k0 - q0;
        const bool nearT = (dq >= -64 && dq <= 128);
        const bool leftT = dq < 0;

        // S = Q K^T per j-tile; exp + classify; store P into OFFQ (warp rows)
        #pragma unroll
        for (int j = 0; j < 8; j++) {
            float sfr[2][4];
            #pragma unroll
            for (int i = 0; i < 2; i++)
                #pragma unroll
                for (int r = 0; r < 4; r++) sfr[i][r] = 0.f;
            #pragma unroll
            for (int c = 0; c < 4; c++) {
                uint2 tb = *(const uint2*)&sm16[OFFK + (j*8+grp)*AQS + c*16 + 4*l4];
                unsigned bf2[2] = {tb.x, tb.y};
                mma_f16(sfr[0], qf[0][c], bf2);
                mma_f16(sfr[1], qf[1][c], bf2);
            }
            const int po = (j>>1)*16 + ((j&1) ? 4*l4+2 : 4*l4);
            if (nearT) {
                #pragma unroll
                for (int i = 0; i < 2; i++)
                    #pragma unroll
                    for (int hh = 0; hh < 2; hh++) {
                        int rr = rl[i][hh];
                        float pp[2];
                        #pragma unroll
                        for (int par = 0; par < 2; par++) {
                            int col = j*8 + l4*2 + par;
                            int dlt = k0 + col - (q0 + rr);
                            int ix = min(max(dlt, -50), 50) + 50;
                            float qd = __half2float(qdp[rr*104 + ix]);
                            float pv = exp2f((sfr[i][hh*2+par] + qd) * C8);
                            if (dlt <= -50)     lft[i][hh] += pv;
                            else if (dlt >= 50) rgt[i][hh] += pv;
                            else pbd[rr*100 + dlt + 49] = __float2half(pv);
                            pp[par] = pv;
                        }
                        *(__half2*)&sm16[OFFQ + rr*AQS + po] = __floats2half2_rn(pp[0], pp[1]);
                    }
            } else {
                #pragma unroll
                for (int i = 0; i < 2; i++)
                    #pragma unroll
                    for (int hh = 0; hh < 2; hh++) {
                        int rr = rl[i][hh];
                        float qc = leftT ? qlC[i][hh] : qrC[i][hh];
                        float pv0 = exp2f(fmaf(sfr[i][hh*2+0], C8, qc));
                        float pv1 = exp2f(fmaf(sfr[i][hh*2+1], C8, qc));
                        if (leftT) lft[i][hh] += pv0 + pv1;
                        else       rgt[i][hh] += pv0 + pv1;
                        *(__half2*)&sm16[OFFQ + rr*AQS + po] = __floats2half2_rn(pv0, pv1);
                    }
            }
        }
        __syncwarp();

        // O += P V : A-frags from P (OFFQ), ldsm V B-frags shared across i
        #pragma unroll
        for (int c = 0; c < 4; c++) {
            unsigned af[2][4];
            #pragma unroll
            for (int i = 0; i < 2; i++) {
                uint2 t0 = *(const uint2*)&sm16[OFFQ + rl[i][0]*AQS + c*16 + 4*l4];
                uint2 t1 = *(const uint2*)&sm16[OFFQ + rl[i][1]*AQS + c*16 + 4*l4];
                af[i][0] = t0.x; af[i][1] = t1.x; af[i][2] = t0.y; af[i][3] = t1.y;
            }
            #pragma unroll
            for (int jj = 0; jj < 8; jj += 2) {
                unsigned r0, r1, r2, r3;
                int mm = lane >> 3, rs = lane & 7;
                uint32_t ad = smb + 2u*(OFFV + (c*16 + (mm&1)*8 + rs)*AVS + (jj + (mm>>1))*8);
                ldsm_x4_trans(r0, r1, r2, r3, ad);
                unsigned b0[2] = {r0, r1}, b1[2] = {r2, r3};
                mma_f16(oacc[0][jj],   af[0], b0);
                mma_f16(oacc[0][jj+1], af[0], b1);
                mma_f16(oacc[1][jj],   af[1], b0);
                mma_f16(oacc[1][jj+1], af[1], b1);
            }
        }
        __syncthreads();
    }

    // quad-reduce clip masses
    #pragma unroll
    for (int i = 0; i < 2; i++)
        #pragma unroll
        for (int hh = 0; hh < 2; hh++) {
            lft[i][hh] += __shfl_xor_sync(0xffffffffu, lft[i][hh], 1);
            lft[i][hh] += __shfl_xor_sync(0xffffffffu, lft[i][hh], 2);
            rgt[i][hh] += __shfl_xor_sync(0xffffffffu, rgt[i][hh], 1);
            rgt[i][hh] += __shfl_xor_sync(0xffffffffu, rgt[i][hh], 2);
        }

    // rel_v fp16 plain [101][64] into dead K region
    #pragma unroll
    for (int s = 0; s < 13; s++) {
        int i = tid + s*128;
        if (i < NR*16) {
            int r = i >> 4, c4 = (i & 15)*4;
            float4 v = *(const float4*)(rel_v + r*DHD + c4);
            __half2* dst = (__half2*)&sm16[OFFK + r*64 + c4];
            dst[0] = __floats2half2_rn(v.x, v.y);
            dst[1] = __floats2half2_rn(v.z, v.w);
        }
    }
    __syncthreads();

    float w2a[2][8][4];
    #pragma unroll
    for (int i = 0; i < 2; i++)
        #pragma unroll
        for (int j = 0; j < 8; j++)
            #pragma unroll
            for (int r = 0; r < 4; r++) w2a[i][j][r] = 0.f;
    float bsum[2][2] = {{0.f,0.f},{0.f,0.f}};
    for (int bnd = 0; bnd < 99; bnd++) {
        float pv[2][2];
        #pragma unroll
        for (int i = 0; i < 2; i++)
            #pragma unroll
            for (int hh = 0; hh < 2; hh++) {
                pv[i][hh] = __half2float(pbd[rl[i][hh]*100 + bnd]);
                bsum[i][hh] += pv[i][hh];
            }
        const __half* rv = &sm16[OFFK + (bnd+1)*64 + l4*2];
        #pragma unroll
        for (int j = 0; j < 8; j++) {
            float2 rr = __half22float2(*(const __half2*)&rv[j*8]);
            #pragma unroll
            for (int i = 0; i < 2; i++) {
                w2a[i][j][0] += pv[i][0]*rr.x; w2a[i][j][1] += pv[i][0]*rr.y;
                w2a[i][j][2] += pv[i][1]*rr.x; w2a[i][j][3] += pv[i][1]*rr.y;
            }
        }
    }
    {
        const __half* rvL = &sm16[OFFK + 0*64   + l4*2];
        const __half* rvR = &sm16[OFFK + 100*64 + l4*2];
        #pragma unroll
        for (int j = 0; j < 8; j++) {
            float2 L = __half22float2(*(const __half2*)&rvL[j*8]);
            float2 R = __half22float2(*(const __half2*)&rvR[j*8]);
            #pragma unroll
            for (int i = 0; i < 2; i++) {
                w2a[i][j][0] += lft[i][0]*L.x + rgt[i][0]*R.x;
                w2a[i][j][1] += lft[i][0]*L.y + rgt[i][0]*R.y;
                w2a[i][j][2] += lft[i][1]*L.x + rgt[i][1]*R.x;
                w2a[i][j][3] += lft[i][1]*L.y + rgt[i][1]*R.y;
            }
        }
    }

    // Ctx: fp16 hid-permuted for gemm_out fast path
    const int b = bh / NH, h = bh % NH;
    float inv[2][2];
    #pragma unroll
    for (int i = 0; i < 2; i++)
        #pragma unroll
        for (int hh = 0; hh < 2; hh++)
            inv[i][hh] = 1.f / (lft[i][hh] + rgt[i][hh] + bsum[i][hh]);
    #pragma unroll
    for (int i = 0; i < 2; i++)
        #pragma unroll
        for (int j = 0; j < 8; j++) {
            int pp = (j & 1) ? 2*l4 + 1 : 2*l4;
            int dcol = (j>>1)*16 + 2*pp;
            size_t o0 = ((size_t)(b*SEQL + q0 + rl[i][0]))*HIDD + h*DHD + dcol;
            size_t o1 = ((size_t)(b*SEQL + q0 + rl[i][1]))*HIDD + h*DHD + dcol;
            *(__half2*)&g_Ctx[o0] = __floats2half2_rn((oacc[i][j][0] + w2a[i][j][0]) * inv[i][0],
                                                      (oacc[i][j][1] + w2a[i][j][1]) * inv[i][0]);
            *(__half2*)&g_Ctx[o1] = __floats2half2_rn((oacc[i][j][2] + w2a[i][j][2]) * inv[i][1],
                                                      (oacc[i][j][3] + w2a[i][j][3]) * inv[i][1]);
        }
}

// ---------------------------------------------------------------------------
extern "C" void kernel_launch(void* const* d_in, const int* in_sizes, int n_in,
                              void* d_out, int out_size)
{
    const float* query = (const float*)d_in[0];
    const float* key   = (const float*)d_in[1];
    const float* value = (const float*)d_in[2];
    const float* Wq    = (const float*)d_in[3];
    const float* bq    = (const float*)d_in[4];
    const float* Wk    = (const float*)d_in[5];
    const float* bk    = (const float*)d_in[6];
    const float* Wv    = (const float*)d_in[7];
    const float* bv    = (const float*)d_in[8];
    const float* Wo    = (const float*)d_in[9];
    const float* bo    = (const float*)d_in[10];
    const float* rel_k = (const float*)d_in[11];
    const float* rel_v = (const float*)d_in[12];
    float* out = (float*)d_out;

    dim3 gp((SEQL*BATCH*HIDD/16 + 255)/256, 7);
    preh<<<gp, 256>>>(query, key, value, Wq, Wk, Wv, Wo);

    dim3 gq(32, 8, 3);
    gemm_qkv<<<gq, 128>>>(bq, bk, bv);

    cudaFuncSetAttribute(attn_h, cudaFuncAttributeMaxDynamicSharedMemorySize,
                         ATT_SMEM_BYTES);
    dim3 ga(SEQL / 128, BATCH * NH);
    attn_h<<<ga, 128, ATT_SMEM_BYTES>>>(rel_k, rel_v);

    dim3 gg(32, 8);
    gemm_out_h<<<gg, 128>>>(bo, out);
}